// round 15
// baseline (speedup 1.0000x reference)
#include <cuda_runtime.h>

#define Wd 512
#define Hd 256
#define Bd 4
#define HW (Hd*Wd)
#define NP (Bd*HW)

typedef unsigned long long u64;

// Scratch (static __device__ arrays; no cudaMalloc allowed)
__device__ float4 g_w4[6*NP];  // weights k=0..23 packed as float4 planes
__device__ float  g_w1[NP];    // weight k=24
__device__ float  g_is[NP];    // 1/sum(w)
__device__ float  g_PA[3*NP];
__device__ float  g_PB[3*NP];

// ---- f32x2 packed helpers (sm_100a: SASS FFMA2/FMUL2 via PTX f32x2) ----
static __device__ __forceinline__ u64 pk2(float lo, float hi) {
    u64 r; asm("mov.b64 %0, {%1, %2};" : "=l"(r) : "f"(lo), "f"(hi)); return r;
}
static __device__ __forceinline__ void upk2(float& lo, float& hi, u64 v) {
    asm("mov.b64 {%0, %1}, %2;" : "=f"(lo), "=f"(hi) : "l"(v));
}
static __device__ __forceinline__ u64 fma2(u64 a, u64 b, u64 c) {
    u64 d; asm("fma.rn.f32x2 %0, %1, %2, %3;" : "=l"(d) : "l"(a), "l"(b), "l"(c));
    return d;
}
static __device__ __forceinline__ u64 mul2(u64 a, u64 b) {
    u64 d; asm("mul.rn.f32x2 %0, %1, %2;" : "=l"(d) : "l"(a), "l"(b));
    return d;
}

// ===========================================================================
// k_pre (R12 best-measured shape, unchanged): V=1, 256 threads, 48 regs.
// ===========================================================================
#define PTX_ 32
#define PTY_ 8
#define PSW (PTX_+4)    // 36
#define PSH (PTY_+4)    // 12

__global__ __launch_bounds__(256,5) void k_pre(const float* __restrict__ pts,
                                               const float* __restrict__ nrm,
                                               float* __restrict__ P1)
{
    __shared__ float4 sP [PSH][PSW];   // (Px,Py,Pz,|P|^2)
    __shared__ float4 sND[PSH][PSW];   // (Nx,Ny,Nz,D)  D = N.P
    const int b  = blockIdx.z;
    const int x0 = blockIdx.x*PTX_, y0 = blockIdx.y*PTY_;
    const float* pb = pts + b*3*HW;
    const float* nb = nrm + b*3*HW;

    for (int i = threadIdx.y*PTX_ + threadIdx.x; i < PSW*PSH; i += 256) {
        int cy = i/PSW, cx = i - cy*PSW;
        int gx = x0+cx-2, gy = y0+cy-2;
        float px=0.f,py=0.f,pz=0.f,nx=0.f,ny=0.f,nz=0.f;
        if ((unsigned)gx < Wd && (unsigned)gy < Hd) {
            int o = gy*Wd + gx;
            px = pb[o]; py = pb[o+HW]; pz = pb[o+2*HW];
            nx = nb[o]; ny = nb[o+HW]; nz = nb[o+2*HW];
        }
        sP [cy][cx] = make_float4(px,py,pz, px*px + py*py + pz*pz);
        sND[cy][cx] = make_float4(nx,ny,nz, px*nx + py*ny + pz*nz);
    }
    __syncthreads();

    const int tx = threadIdx.x, ty = threadIdx.y;
    const int cx = tx+2, cy = ty+2;
    const float4 pc = sP[cy][cx];
    const float4 nc = sND[cy][cx];
    const float pix_ = pc.x, piy = pc.y, piz = pc.z, pi2 = pc.w;
    const float nix  = nc.x, niy = nc.y, niz = nc.z;

    float maxn2 = 0.f;
    #pragma unroll
    for (int k = 0; k < 25; k++) {
        int dy = k/5 - 2, dx = k%5 - 2;
        float4 p = sP[cy+dy][cx+dx];
        float d2 = (p.w + pi2) - 2.f*(p.x*pix_ + p.y*piy + p.z*piz);
        maxn2 = fmaxf(maxn2, d2);
    }
    float sig    = sqrtf(maxn2)*0.2f + 1e-5f;
    float nscale = -0.5f/(sig*sig);

    const int gx = x0+tx, gy = y0+ty;
    const int pixid = (b*Hd + gy)*Wd + gx;
    float wsum = 0.f, ix=0.f, iy=0.f, iz=0.f;
    float s0=0.f, s1=0.f, s2=0.f;
    #pragma unroll
    for (int k = 0; k < 25; k++) {
        int dy = k/5 - 2, dx = k%5 - 2;
        float4 p  = sP [cy+dy][cx+dx];
        float4 nd = sND[cy+dy][cx+dx];
        float d2   = (p.w + pi2) - 2.f*(p.x*pix_ + p.y*piy + p.z*piz);
        float cosv = nix*nd.x + niy*nd.y + niz*nd.z;
        float e = 1.f - cosv;
        float w = __expf(d2*nscale - 4.5f*e*e);
        wsum += w;
        float dot = nd.w - (nd.x*pix_ + nd.y*piy + nd.z*piz);
        float t = w*dot;
        ix += t*nd.x; iy += t*nd.y; iz += t*nd.z;
        int j = k & 3;
        if (k == 24)      g_w1[pixid] = w;
        else if (j == 0)  s0 = w;
        else if (j == 1)  s1 = w;
        else if (j == 2)  s2 = w;
        else              g_w4[(k>>2)*NP + pixid] = make_float4(s0, s1, s2, w);
    }
    float invsum = 1.f/wsum;
    g_is[pixid] = invsum;

    const int o = b*3*HW + gy*Wd + gx;
    P1[o]      = pix_ + ix*invsum;
    P1[o+HW]   = piy  + iy*invsum;
    P1[o+2*HW] = piz  + iz*invsum;
}

// ===========================================================================
// k_iter: V=2 vertical pixel pair per thread, f32x2-packed tap math.
// Shared layout = vertical-pair entries so LDS.128 yields lane-paired
// 64-bit operands directly (no packing movs in the loop).
// ===========================================================================
#define ITX 32
#define ITY 4
#define ITILEH 8          // 4 warps x 2 pixel rows
#define ISW (ITX+4)       // 36
#define ISROWS (ITILEH+4) // scalar rows local -2..9 -> 12
#define IEROWS (ITILEH+3) // entry rows: er holds scalar rows (er, er+1) -> 11

template<bool LAST>
__global__ __launch_bounds__(128,8) void k_iter(const float* __restrict__ Pcur,
                                                const float* __restrict__ nrm,
                                                const float* __restrict__ ptsOrig,
                                                float* __restrict__ Pout)
{
    __shared__ float4     sRow[ISROWS][ISW];  // {nx,ny,nz,D}, D = N.Pcur
    __shared__ ulonglong2 sV1 [IEROWS][ISW];  // {(nxA,nxB),(nyA,nyB)}
    __shared__ ulonglong2 sV2 [IEROWS][ISW];  // {(nzA,nzB),(DA,DB)}

    const int b  = blockIdx.z;
    const int x0 = blockIdx.x*ITX, y0 = blockIdx.y*ITILEH;
    const int tx = threadIdx.x, ty = threadIdx.y;
    const int tid = ty*ITX + tx;
    const float* pb = Pcur + b*3*HW;
    const float* nb = nrm  + b*3*HW;

    // Phase 1: scalar rows
    for (int i = tid; i < ISROWS*ISW; i += 128) {
        int cy = i/ISW, cx = i - cy*ISW;
        int gx = x0+cx-2, gy = y0+cy-2;
        float px=0.f,py=0.f,pz=0.f,nx=0.f,ny=0.f,nz=0.f;
        if ((unsigned)gx < Wd && (unsigned)gy < Hd) {
            int o = gy*Wd + gx;
            px = pb[o]; py = pb[o+HW]; pz = pb[o+2*HW];
            nx = nb[o]; ny = nb[o+HW]; nz = nb[o+2*HW];
        }
        sRow[cy][cx] = make_float4(nx,ny,nz, px*nx + py*ny + pz*nz);
    }
    __syncthreads();

    // Phase 2: build vertical-pair entries
    for (int i = tid; i < IEROWS*ISW; i += 128) {
        int er = i/ISW, cx = i - er*ISW;
        float4 a = sRow[er][cx];
        float4 c = sRow[er+1][cx];
        ulonglong2 v1, v2;
        v1.x = pk2(a.x, c.x); v1.y = pk2(a.y, c.y);
        v2.x = pk2(a.z, c.z); v2.y = pk2(a.w, c.w);
        sV1[er][cx] = v1;
        sV2[er][cx] = v2;
    }
    __syncthreads();

    // Pixel pair: A = row y0+r0, B = row y0+r0+1
    const int r0  = ty*2;
    const int gx  = x0+tx;
    const int gyA = y0+r0;
    const int idA = (b*Hd + gyA)*Wd + gx;
    const int idB = idA + Wd;
    const int oA  = b*3*HW + gyA*Wd + gx;
    const int oB  = oA + Wd;

    const float pAx = Pcur[oA], pAy = Pcur[oA+HW], pAz = Pcur[oA+2*HW];
    const float pBx = Pcur[oB], pBy = Pcur[oB+HW], pBz = Pcur[oB+2*HW];

    // negated packed center coords: dot accumulates D + (-P).N
    const u64 nPx = pk2(-pAx, -pBx);
    const u64 nPy = pk2(-pAy, -pBy);
    const u64 nPz = pk2(-pAz, -pBz);

    u64 ax2 = 0, ay2 = 0, az2 = 0;   // bit pattern 0 == (0.f,0.f)
    float4 qA, qB;
    float w24A = 0.f, w24B = 0.f;

    #pragma unroll
    for (int k = 0; k < 25; k++) {
        const int j = k/5, dx = k%5;
        ulonglong2 e1 = sV1[r0+j][tx+dx];
        ulonglong2 e2 = sV2[r0+j][tx+dx];
        // dot = D - N.P  (per lane)
        u64 dot = fma2(e1.x, nPx, e2.y);
        dot = fma2(e1.y, nPy, dot);
        dot = fma2(e2.x, nPz, dot);
        // weights
        float wA, wB;
        if (k == 24) {
            w24A = g_w1[idA]; w24B = g_w1[idB];
            wA = w24A; wB = w24B;
        } else {
            int m = k & 3;
            if (m == 0) { qA = g_w4[(k>>2)*NP + idA]; qB = g_w4[(k>>2)*NP + idB]; }
            wA = (m==0)?qA.x:(m==1)?qA.y:(m==2)?qA.z:qA.w;
            wB = (m==0)?qB.x:(m==1)?qB.y:(m==2)?qB.z:qB.w;
        }
        u64 t2 = mul2(pk2(wA, wB), dot);
        ax2 = fma2(t2, e1.x, ax2);
        ay2 = fma2(t2, e1.y, ay2);
        az2 = fma2(t2, e2.x, az2);
    }

    float axA, axB, ayA, ayB, azA, azB;
    upk2(axA, axB, ax2);
    upk2(ayA, ayB, ay2);
    upk2(azA, azB, az2);

    const float isA = g_is[idA], isB = g_is[idB];
    float oxA = pAx + axA*isA, oyA = pAy + ayA*isA, ozA = pAz + azA*isA;
    float oxB = pBx + axB*isB, oyB = pBy + ayB*isB, ozB = pBz + azB*isB;
    if (LAST) {
        oxA = (ptsOrig[oA]      != 0.f) ? oxA : 0.f;
        oyA = (ptsOrig[oA+HW]   != 0.f) ? oyA : 0.f;
        ozA = (ptsOrig[oA+2*HW] != 0.f) ? ozA : 0.f;
        oxB = (ptsOrig[oB]      != 0.f) ? oxB : 0.f;
        oyB = (ptsOrig[oB+HW]   != 0.f) ? oyB : 0.f;
        ozB = (ptsOrig[oB+2*HW] != 0.f) ? ozB : 0.f;
    }
    Pout[oA] = oxA; Pout[oA+HW] = oyA; Pout[oA+2*HW] = ozA;
    Pout[oB] = oxB; Pout[oB+HW] = oyB; Pout[oB+2*HW] = ozB;
}

extern "C" void kernel_launch(void* const* d_in, const int* in_sizes, int n_in,
                              void* d_out, int out_size)
{
    const float* pts = (const float*)d_in[0];
    const float* nrm = (const float*)d_in[1];
    float* out = (float*)d_out;

    float *PA, *PB;
    cudaGetSymbolAddress((void**)&PA, g_PA);
    cudaGetSymbolAddress((void**)&PB, g_PB);

    dim3 pblock(PTX_, PTY_);
    dim3 pgrid(Wd/PTX_, Hd/PTY_, Bd);     // 16 x 32 x 4

    dim3 iblock(ITX, ITY);
    dim3 igrid(Wd/ITX, Hd/ITILEH, Bd);    // 16 x 32 x 4

    k_pre<<<pgrid, pblock>>>(pts, nrm, PA);               // weights + iter 1
    k_iter<false><<<igrid, iblock>>>(PA, nrm, pts, PB);   // iter 2
    k_iter<true ><<<igrid, iblock>>>(PB, nrm, pts, out);  // iter 3 + mask
}

// round 16
// speedup vs baseline: 1.1439x; 1.1439x over previous
#include <cuda_runtime.h>

#define Wd 512
#define Hd 256
#define Bd 4
#define HW (Hd*Wd)
#define NP (Bd*HW)

// Scratch (static __device__ arrays; no cudaMalloc allowed)
__device__ float4 g_w4[6*NP];  // weights k=0..23 packed as float4 planes
__device__ float  g_w1[NP];    // weight k=24
__device__ float  g_is[NP];    // 1/sum(w)
__device__ float  g_PA[3*NP];
__device__ float  g_PB[3*NP];

static __device__ __forceinline__ float ex2f(float x) {
    float r; asm("ex2.approx.ftz.f32 %0, %1;" : "=f"(r) : "f"(x)); return r;
}

// ===========================================================================
// k_pre: V=1, 256 threads (best measured shape) + strength-reduced tap math.
//   pass1: t = |Pk|^2 - 2 Pk.Pi  (3 FMA + max); maxn2 = max(t) + |Pi|^2
//   pass2: w = ex2( fma(nsL,t,CL) + cos*fma(-4.5L,cos,9L) ),  L = log2(e)
// ===========================================================================
#define PTX_ 32
#define PTY_ 8
#define PSW (PTX_+4)    // 36
#define PSH (PTY_+4)    // 12

__global__ __launch_bounds__(256,5) void k_pre(const float* __restrict__ pts,
                                               const float* __restrict__ nrm,
                                               float* __restrict__ P1)
{
    __shared__ float4 sP [PSH][PSW];   // (Px,Py,Pz,|P|^2)
    __shared__ float4 sND[PSH][PSW];   // (Nx,Ny,Nz,D)  D = N.P
    const int b  = blockIdx.z;
    const int x0 = blockIdx.x*PTX_, y0 = blockIdx.y*PTY_;
    const float* pb = pts + b*3*HW;
    const float* nb = nrm + b*3*HW;

    for (int i = threadIdx.y*PTX_ + threadIdx.x; i < PSW*PSH; i += 256) {
        int cy = i/PSW, cx = i - cy*PSW;
        int gx = x0+cx-2, gy = y0+cy-2;
        float px=0.f,py=0.f,pz=0.f,nx=0.f,ny=0.f,nz=0.f;
        if ((unsigned)gx < Wd && (unsigned)gy < Hd) {
            int o = gy*Wd + gx;
            px = pb[o]; py = pb[o+HW]; pz = pb[o+2*HW];
            nx = nb[o]; ny = nb[o+HW]; nz = nb[o+2*HW];
        }
        sP [cy][cx] = make_float4(px,py,pz, px*px + py*py + pz*pz);
        sND[cy][cx] = make_float4(nx,ny,nz, px*nx + py*ny + pz*nz);
    }
    __syncthreads();

    const int tx = threadIdx.x, ty = threadIdx.y;
    const int cx = tx+2, cy = ty+2;
    const float4 pc = sP[cy][cx];
    const float4 nc = sND[cy][cx];
    const float pix_ = pc.x, piy = pc.y, piz = pc.z, pi2 = pc.w;
    const float nix  = nc.x, niy = nc.y, niz = nc.z;

    // hoisted constants for the tap loops
    const float m2x = -2.f*pix_, m2y = -2.f*piy, m2z = -2.f*piz;
    const float npx = -pix_,     npy = -piy,     npz = -piz;

    // Pass 1: maxt = max over taps of (|Pk|^2 - 2 Pk.Pi)
    float maxt = -3.402823466e38f;
    #pragma unroll
    for (int k = 0; k < 25; k++) {
        int dy = k/5 - 2, dx = k%5 - 2;
        float4 p = sP[cy+dy][cx+dx];
        float t = fmaf(m2x, p.x, fmaf(m2y, p.y, fmaf(m2z, p.z, p.w)));
        maxt = fmaxf(maxt, t);
    }
    float maxn2  = fmaxf(maxt + pi2, 0.f);
    float sig    = sqrtf(maxn2)*0.2f + 1e-5f;
    float nscale = -0.5f/(sig*sig);

    // exp-argument constants (folded log2(e))
    const float L    = 1.4426950408889634f;
    const float nsL  = nscale*L;
    const float CL   = (nscale*pi2 - 4.5f)*L;
    const float A45L = -4.5f*L;      // -6.49212768
    const float N9L  = 9.f*L;        // 12.98425537

    // Pass 2: weights + wsum + unnormalized first-iter improvement.
    const int gx = x0+tx, gy = y0+ty;
    const int pixid = (b*Hd + gy)*Wd + gx;
    float wsum = 0.f, ix=0.f, iy=0.f, iz=0.f;
    float s0=0.f, s1=0.f, s2=0.f;
    #pragma unroll
    for (int k = 0; k < 25; k++) {
        int dy = k/5 - 2, dx = k%5 - 2;
        float4 p  = sP [cy+dy][cx+dx];
        float4 nd = sND[cy+dy][cx+dx];
        float t    = fmaf(m2x, p.x, fmaf(m2y, p.y, fmaf(m2z, p.z, p.w)));
        float cosv = fmaf(nix, nd.x, fmaf(niy, nd.y, niz*nd.z));
        float argL = fmaf(cosv, fmaf(A45L, cosv, N9L), fmaf(nsL, t, CL));
        float w = ex2f(argL);
        wsum += w;
        float dot = fmaf(nd.x, npx, fmaf(nd.y, npy, fmaf(nd.z, npz, nd.w)));
        float tt = w*dot;
        ix = fmaf(tt, nd.x, ix); iy = fmaf(tt, nd.y, iy); iz = fmaf(tt, nd.z, iz);
        int j = k & 3;
        if (k == 24)      g_w1[pixid] = w;
        else if (j == 0)  s0 = w;
        else if (j == 1)  s1 = w;
        else if (j == 2)  s2 = w;
        else              g_w4[(k>>2)*NP + pixid] = make_float4(s0, s1, s2, w);
    }
    float invsum = 1.f/wsum;
    g_is[pixid] = invsum;

    const int o = b*3*HW + gy*Wd + gx;
    P1[o]      = pix_ + ix*invsum;
    P1[o+HW]   = piy  + iy*invsum;
    P1[o+2*HW] = piz  + iz*invsum;
}

// ===========================================================================
// k_iter: V=2 vertical pixels/thread, scalar math (best measured: 12.7us).
// P_out = P_cur + invsum*sum_k w_k (D_k - N_k.P_i) N_k
// ===========================================================================
#define ITX 32
#define ITY 8
#define IVY 2
#define ITILEH (ITY*IVY)   // 16
#define ISW (ITX+4)        // 36
#define ISH (ITILEH+4)     // 20

template<bool LAST>
__global__ __launch_bounds__(256,4) void k_iter(const float* __restrict__ Pcur,
                                                const float* __restrict__ nrm,
                                                const float* __restrict__ ptsOrig,
                                                float* __restrict__ Pout)
{
    __shared__ float4 sND[ISH][ISW];   // (Nx,Ny,Nz,D) with D = N.Pcur
    const int b  = blockIdx.z;
    const int x0 = blockIdx.x*ITX, y0 = blockIdx.y*ITILEH;
    const float* pb = Pcur + b*3*HW;
    const float* nb = nrm  + b*3*HW;

    for (int i = threadIdx.y*ITX + threadIdx.x; i < ISW*ISH; i += 256) {
        int cy = i/ISW, cx = i - cy*ISW;
        int gx = x0+cx-2, gy = y0+cy-2;
        float px=0.f,py=0.f,pz=0.f,nx=0.f,ny=0.f,nz=0.f;
        if ((unsigned)gx < Wd && (unsigned)gy < Hd) {
            int o = gy*Wd + gx;
            px = pb[o]; py = pb[o+HW]; pz = pb[o+2*HW];
            nx = nb[o]; ny = nb[o+HW]; nz = nb[o+2*HW];
        }
        sND[cy][cx] = make_float4(nx,ny,nz, px*nx + py*ny + pz*nz);
    }
    __syncthreads();

    const int tx = threadIdx.x, ty = threadIdx.y;
    const int r0 = ty*IVY;
    const int gx = x0+tx;
    const int gyA = y0+r0;
    const int idA = (b*Hd + gyA)*Wd + gx;
    const int idB = idA + Wd;
    const int oA  = b*3*HW + gyA*Wd + gx;
    const int oB  = oA + Wd;

    const float pAx = Pcur[oA],    pAy = Pcur[oA+HW],    pAz = Pcur[oA+2*HW];
    const float pBx = Pcur[oB],    pBy = Pcur[oB+HW],    pBz = Pcur[oB+2*HW];
    const float isA = g_is[idA],   isB = g_is[idB];

    float axA=0.f, ayA=0.f, azA=0.f;
    float axB=0.f, ayB=0.f, azB=0.f;
    float4 qA = make_float4(0,0,0,0), qB = make_float4(0,0,0,0);
    #pragma unroll
    for (int j = 0; j < 6; j++) {
        #pragma unroll
        for (int dx = 0; dx < 5; dx++) {
            float4 nd = sND[r0+j][tx+dx];
            if (j <= 4) {
                int k = j*5 + dx;
                float w;
                if (k == 24) w = g_w1[idA];
                else {
                    int m = k & 3;
                    if (m == 0) qA = g_w4[(k>>2)*NP + idA];
                    w = (m==0)?qA.x:(m==1)?qA.y:(m==2)?qA.z:qA.w;
                }
                float dot = nd.w - (nd.x*pAx + nd.y*pAy + nd.z*pAz);
                float t = w*dot;
                axA += t*nd.x; ayA += t*nd.y; azA += t*nd.z;
            }
            if (j >= 1) {
                int k = (j-1)*5 + dx;
                float w;
                if (k == 24) w = g_w1[idB];
                else {
                    int m = k & 3;
                    if (m == 0) qB = g_w4[(k>>2)*NP + idB];
                    w = (m==0)?qB.x:(m==1)?qB.y:(m==2)?qB.z:qB.w;
                }
                float dot = nd.w - (nd.x*pBx + nd.y*pBy + nd.z*pBz);
                float t = w*dot;
                axB += t*nd.x; ayB += t*nd.y; azB += t*nd.z;
            }
        }
    }

    float oxA = pAx + axA*isA, oyA = pAy + ayA*isA, ozA = pAz + azA*isA;
    float oxB = pBx + axB*isB, oyB = pBy + ayB*isB, ozB = pBz + azB*isB;
    if (LAST) {
        oxA = (ptsOrig[oA]      != 0.f) ? oxA : 0.f;
        oyA = (ptsOrig[oA+HW]   != 0.f) ? oyA : 0.f;
        ozA = (ptsOrig[oA+2*HW] != 0.f) ? ozA : 0.f;
        oxB = (ptsOrig[oB]      != 0.f) ? oxB : 0.f;
        oyB = (ptsOrig[oB+HW]   != 0.f) ? oyB : 0.f;
        ozB = (ptsOrig[oB+2*HW] != 0.f) ? ozB : 0.f;
    }
    Pout[oA] = oxA; Pout[oA+HW] = oyA; Pout[oA+2*HW] = ozA;
    Pout[oB] = oxB; Pout[oB+HW] = oyB; Pout[oB+2*HW] = ozB;
}

extern "C" void kernel_launch(void* const* d_in, const int* in_sizes, int n_in,
                              void* d_out, int out_size)
{
    const float* pts = (const float*)d_in[0];
    const float* nrm = (const float*)d_in[1];
    float* out = (float*)d_out;

    float *PA, *PB;
    cudaGetSymbolAddress((void**)&PA, g_PA);
    cudaGetSymbolAddress((void**)&PB, g_PB);

    dim3 pblock(PTX_, PTY_);
    dim3 pgrid(Wd/PTX_, Hd/PTY_, Bd);     // 16 x 32 x 4

    dim3 iblock(ITX, ITY);
    dim3 igrid(Wd/ITX, Hd/ITILEH, Bd);    // 16 x 16 x 4

    k_pre<<<pgrid, pblock>>>(pts, nrm, PA);               // weights + iter 1
    k_iter<false><<<igrid, iblock>>>(PA, nrm, pts, PB);   // iter 2
    k_iter<true ><<<igrid, iblock>>>(PB, nrm, pts, out);  // iter 3 + mask
}